// round 8
// baseline (speedup 1.0000x reference)
#include <cuda_runtime.h>
#include <math.h>

#define BB 16
#define HW 65536            // 256*256
#define NPIX (BB*HW)        // 1048576
#define WPR 8               // u32 words per row
#define WPS 2048            // words per sample
#define NWORDS 32768
#define NB 512              // 16 samples * 32 row-groups (8 rows each)
#define TPB 128
#define WLCAP 65536

// ---- device scratch (allocation-free). Reset by final block each replay. ----
__device__ unsigned g_posbits[NWORDS];
__device__ double g_ce;
__device__ int    g_hard_i, g_t_i, g_inter_i;
__device__ double g_res[BB];
__device__ int    g_haspos[BB];
__device__ int    g_hasneg[BB];
__device__ unsigned g_ticket;
__device__ int    g_wl_n;
__device__ int    g_wl[WLCAP];

__device__ __forceinline__ unsigned smem_u32(const void* p) {
    unsigned a;
    asm("{ .reg .u64 t; cvta.to.shared.u64 t, %1; cvt.u32.u64 %0, t; }" : "=r"(a) : "l"(p));
    return a;
}

// ---------------------------------------------------------------------------
// Exact fallback (P ~ 2^-24 per target pixel; runs in final block only)
// ---------------------------------------------------------------------------
__device__ __forceinline__ int row_mindx(const unsigned* __restrict__ row, int j, unsigned inv) {
    int wj = j >> 5, off = j & 31;
    int best = 30000;
    unsigned m = (row[wj] ^ inv) >> off;
    if (m) best = __ffs(m) - 1;
    else {
        for (int w = wj + 1; w < WPR; ++w) {
            unsigned x = row[w] ^ inv;
            if (x) { best = 32 * (w - wj) - off + __ffs(x) - 1; break; }
        }
    }
    unsigned ml = (row[wj] ^ inv) << (31 - off);
    if (ml) { int d = __clz(ml); best = min(best, d); }
    else {
        for (int w = wj - 1; w >= 0; --w) {
            unsigned x = row[w] ^ inv;
            if (x) { int d = j - (32 * w + 31 - __clz(x)); best = min(best, d); break; }
        }
    }
    return best;
}

__device__ double fb_contrib(const unsigned* __restrict__ bp, int i, int j, int mybit,
                             int haspos, int hasneg) {
    float d;
    if (!haspos || !hasneg) {
        d = 1.0e9f;                      // reference BIG
    } else {
        unsigned inv = mybit ? 0xffffffffu : 0u;
        int best2 = 1 << 30;
        for (int dy = 0; dy < 256; ++dy) {
            int dy2 = dy * dy;
            if (dy2 >= best2) break;
            int up = i - dy, dn = i + dy;
            if (up >= 0) {
                int dx = row_mindx(bp + up * WPR, j, inv);
                int d2 = dy2 + dx * dx;
                if (d2 < best2) best2 = d2;
            }
            if (dy && dn < 256) {
                int dx = row_mindx(bp + dn * WPR, j, inv);
                int d2 = dy2 + dx * dx;
                if (d2 < best2) best2 = d2;
            }
        }
        d = sqrtf((float)best2);
    }
    return mybit ? -(double)(d - 1.0f) : (double)d;
}

// ---------------------------------------------------------------------------
// One kernel: bulk-async tile -> SMEM, compute from SMEM, SMEM phase 2.
// ---------------------------------------------------------------------------
__global__ __launch_bounds__(TPB)
void k_fused(const float* __restrict__ inp, const int* __restrict__ tgt,
             float* __restrict__ out, int out_size) {
    __shared__ __align__(16) float s_in0[12 * 256];   // ch0, rows r0-2..r0+9
    __shared__ __align__(16) float s_in1[12 * 256];   // ch1
    __shared__ __align__(16) int   s_tgt[8 * 256];    // main rows only
    __shared__ __align__(8)  unsigned long long s_mbar;
    __shared__ unsigned short sh_ph16[8 * 16];
    __shared__ unsigned short sh_th16[8 * 16];
    __shared__ unsigned char  sh_hb[4 * 32];
    __shared__ unsigned sh_pw[12 * 8];
    __shared__ unsigned sh_tw[8 * 8];
    __shared__ float  s_ce[4];
    __shared__ int    s_cnt[4], s_fl[4];
    __shared__ float  s_c[2];
    __shared__ bool   s_last;

    int tid = threadIdx.x;
    int blk = blockIdx.x;
    int s   = blk >> 5;            // sample
    int r0  = (blk & 31) << 3;     // first main row

    // ---------------- bulk-async copies into SMEM --------------------------
    unsigned mbar = smem_u32(&s_mbar);
    int glo   = max(r0 - 2, 0);
    int ghi   = min(r0 + 10, 256);          // exclusive
    int nrows = ghi - glo;
    int sroff = glo - (r0 - 2);             // smem row offset of first copied row

    if (tid == 0) {
        asm volatile("mbarrier.init.shared.b64 [%0], %1;" :: "r"(mbar), "r"(1) : "memory");
        asm volatile("fence.proxy.async.shared::cta;" ::: "memory");
    }
    __syncthreads();

    if (tid == 0) {
        unsigned total = (unsigned)(2 * nrows * 1024 + 8 * 1024);
        asm volatile("mbarrier.arrive.expect_tx.shared.b64 _, [%0], %1;"
                     :: "r"(mbar), "r"(total) : "memory");
        const char* src0 = (const char*)(inp + (size_t)(s * 2) * HW + glo * 256);
        const char* src1 = (const char*)(inp + (size_t)(s * 2 + 1) * HW + glo * 256);
        const char* srct = (const char*)(tgt + (size_t)s * HW + r0 * 256);
        unsigned d0 = smem_u32(s_in0) + sroff * 1024;
        unsigned d1 = smem_u32(s_in1) + sroff * 1024;
        unsigned dt = smem_u32(s_tgt);
        asm volatile("cp.async.bulk.shared::cta.global.mbarrier::complete_tx::bytes [%0], [%1], %2, [%3];"
                     :: "r"(d0), "l"(src0), "r"((unsigned)(nrows * 1024)), "r"(mbar) : "memory");
        asm volatile("cp.async.bulk.shared::cta.global.mbarrier::complete_tx::bytes [%0], [%1], %2, [%3];"
                     :: "r"(d1), "l"(src1), "r"((unsigned)(nrows * 1024)), "r"(mbar) : "memory");
        asm volatile("cp.async.bulk.shared::cta.global.mbarrier::complete_tx::bytes [%0], [%1], %2, [%3];"
                     :: "r"(dt), "l"(srct), "r"(8192u), "r"(mbar) : "memory");
    }
    // wait (parity 0)
    {
        unsigned done;
        asm volatile(
            "{\n\t.reg .pred p;\n\t"
            "mbarrier.try_wait.parity.acquire.cta.shared::cta.b64 p, [%1], 0;\n\t"
            "selp.b32 %0, 1, 0, p;\n\t}"
            : "=r"(done) : "r"(mbar) : "memory");
        if (!done) {
            asm volatile(
                "{\n\t.reg .pred P1;\n\t"
                "WL_%=:\n\t"
                "mbarrier.try_wait.parity.acquire.cta.shared::cta.b64 P1, [%0], 0, 0x989680;\n\t"
                "@P1 bra.uni WD_%=;\n\t"
                "bra.uni WL_%=;\n\t"
                "WD_%=:\n\t}"
                :: "r"(mbar) : "memory");
        }
    }

    // ---------------- Phase 1: CE + bits from SMEM (16 px/thread) ----------
    int row_local = tid >> 4;      // 0..7
    int grp       = tid & 15;      // 16-px group
    int row12     = row_local + 2; // smem row index

    const float4* f0 = (const float4*)(s_in0 + row12 * 256 + grp * 16);
    const float4* f1 = (const float4*)(s_in1 + row12 * 256 + grp * 16);
    const int4*   ft = (const int4*)(s_tgt + row_local * 256 + grp * 16);

    float ces = 0.0f;
    unsigned pbits = 0, hbits = 0, tbits = 0;
    #pragma unroll
    for (int q = 0; q < 4; ++q) {
        float4 x0v = f0[q];
        float4 x1v = f1[q];
        int4   tv  = ft[q];
        #define ELEM(K, X0, X1, T) {                                   \
            float x0 = (X0), x1 = (X1); int t = (T);                   \
            float m   = fmaxf(x0, x1);                                 \
            float lse = m + __logf(1.0f + __expf(-fabsf(x1 - x0)));    \
            ces += lse - ((t == 1) ? x1 : x0);                         \
            pbits |= ((unsigned)(x1 > x0))  << (4 * q + K);            \
            hbits |= ((unsigned)(x1 >= x0)) << (4 * q + K);            \
            tbits |= ((unsigned)(t == 1))   << (4 * q + K); }
        ELEM(0, x0v.x, x1v.x, tv.x)
        ELEM(1, x0v.y, x1v.y, tv.y)
        ELEM(2, x0v.z, x1v.z, tv.z)
        ELEM(3, x0v.w, x1v.w, tv.w)
        #undef ELEM
    }
    int hard  = __popc(hbits);
    int tcnt  = __popc(tbits);
    int inter = __popc(hbits & tbits);

    sh_ph16[row_local * 16 + grp] = (unsigned short)pbits;
    sh_th16[row_local * 16 + grp] = (unsigned short)tbits;

    // halo pos bits from SMEM: 4 rows x 256 px, 8 px/thread
    {
        int hr = tid >> 5, hcb = tid & 31;
        int habs   = (hr < 2) ? (r0 - 2 + hr) : (r0 + 8 + (hr - 2));
        int hrow12 = (hr < 2) ? hr : (10 + (hr - 2));
        unsigned hpb = 0;
        if (habs >= 0 && habs <= 255) {
            const float4* h0 = (const float4*)(s_in0 + hrow12 * 256 + hcb * 8);
            const float4* h1 = (const float4*)(s_in1 + hrow12 * 256 + hcb * 8);
            float4 a0 = h0[0], a1 = h0[1], c0 = h1[0], c1 = h1[1];
            hpb |= ((unsigned)(c0.x > a0.x)) << 0;
            hpb |= ((unsigned)(c0.y > a0.y)) << 1;
            hpb |= ((unsigned)(c0.z > a0.z)) << 2;
            hpb |= ((unsigned)(c0.w > a0.w)) << 3;
            hpb |= ((unsigned)(c1.x > a1.x)) << 4;
            hpb |= ((unsigned)(c1.y > a1.y)) << 5;
            hpb |= ((unsigned)(c1.z > a1.z)) << 6;
            hpb |= ((unsigned)(c1.w > a1.w)) << 7;
        }
        sh_hb[hr * 32 + hcb] = (unsigned char)hpb;
    }

    // warp reductions
    unsigned cnt = (unsigned)hard | ((unsigned)tcnt << 10) | ((unsigned)inter << 20);
    unsigned wcnt = __reduce_add_sync(0xffffffffu, cnt);
    unsigned bpos = __ballot_sync(0xffffffffu, pbits != 0u);
    unsigned bneg = __ballot_sync(0xffffffffu, pbits != 0xffffu);
    #pragma unroll
    for (int off = 16; off > 0; off >>= 1)
        ces += __shfl_xor_sync(0xffffffffu, ces, off);
    int wid = tid >> 5;
    if ((tid & 31) == 0) {
        s_ce[wid]  = ces;
        s_cnt[wid] = (int)wcnt;
        s_fl[wid]  = (bpos ? 1 : 0) | (bneg ? 2 : 0);
    }
    __syncthreads();

    // ---------------- word assembly + block atomics ------------------------
    if (tid < 96) {                              // pos words: 12 rows x 8
        int row = tid >> 3, wc = tid & 7;
        unsigned v;
        if (row >= 2 && row <= 9) {
            int mr = row - 2;
            v =  (unsigned)sh_ph16[mr * 16 + 2 * wc]
              | ((unsigned)sh_ph16[mr * 16 + 2 * wc + 1] << 16);
        } else {
            int hrow = (row < 2) ? row : (row - 8);  // 10->2, 11->3
            v =  (unsigned)sh_hb[hrow * 32 + 4 * wc]
              | ((unsigned)sh_hb[hrow * 32 + 4 * wc + 1] << 8)
              | ((unsigned)sh_hb[hrow * 32 + 4 * wc + 2] << 16)
              | ((unsigned)sh_hb[hrow * 32 + 4 * wc + 3] << 24);
        }
        sh_pw[tid] = v;
    }
    if (tid >= 64) {                             // t1 words: 8 rows x 8
        int w = tid - 64;
        int mr = w >> 3, wc = w & 7;
        sh_tw[w] =  (unsigned)sh_th16[mr * 16 + 2 * wc]
                 | ((unsigned)sh_th16[mr * 16 + 2 * wc + 1] << 16);
    }
    if (tid == 0) {
        float bce = 0.0f; int bh = 0, bt = 0, bi = 0, bfl = 0;
        #pragma unroll
        for (int w = 0; w < 4; ++w) {
            bce += s_ce[w];
            unsigned c = (unsigned)s_cnt[w];
            bh += (int)(c & 1023u); bt += (int)((c >> 10) & 1023u); bi += (int)(c >> 20);
            bfl |= s_fl[w];
        }
        atomicAdd(&g_ce, (double)bce);
        atomicAdd(&g_hard_i,  bh);
        atomicAdd(&g_t_i,     bt);
        atomicAdd(&g_inter_i, bi);
        if (bfl & 1) g_haspos[s] = 1;
        if (bfl & 2) g_hasneg[s] = 1;
    }
    __syncthreads();

    // ---------------- Phase 2: 5x5 bit-parallel (64 threads) ---------------
    float contrib = 0.0f;
    if (tid < 64) {
        int wr = tid >> 3, wc = tid & 7;
        int i   = r0 + wr;
        int i12 = wr + 2;

        unsigned P  = sh_pw[i12 * 8 + wc];
        unsigned T1 = sh_tw[wr * 8 + wc];
        g_posbits[s * WPS + i * WPR + wc] = P;   // for worklist fallback only

        unsigned lm1 = (wc == 0) ? 0xfffffffeu : 0xffffffffu;
        unsigned rm1 = (wc == 7) ? 0x7fffffffu : 0xffffffffu;
        unsigned lm2 = (wc == 0) ? 0xfffffffcu : 0xffffffffu;
        unsigned rm2 = (wc == 7) ? 0x3fffffffu : 0xffffffffu;
        unsigned vu1 = (i >= 1)   ? 0xffffffffu : 0u;
        unsigned vu2 = (i >= 2)   ? 0xffffffffu : 0u;
        unsigned vd1 = (i <= 254) ? 0xffffffffu : 0u;
        unsigned vd2 = (i <= 253) ? 0xffffffffu : 0u;

        #define ROWX(r12, XM, X1L, X1R, X2L, X2R) {                      \
            unsigned Lw = (wc > 0) ? sh_pw[(r12) * 8 + wc - 1] : 0u;     \
            unsigned Mw = sh_pw[(r12) * 8 + wc];                         \
            unsigned Rw = (wc < 7) ? sh_pw[(r12) * 8 + wc + 1] : 0u;     \
            XM  = Mw ^ P;                                                \
            X1L = __funnelshift_l(Lw, Mw, 1) ^ P;                        \
            X1R = __funnelshift_r(Mw, Rw, 1) ^ P;                        \
            X2L = __funnelshift_l(Lw, Mw, 2) ^ P;                        \
            X2R = __funnelshift_r(Mw, Rw, 2) ^ P; }

        unsigned m0, l10, r10, l20, r20;      ROWX(i12,     m0,  l10,  r10,  l20,  r20)
        unsigned mu1, l1u1, r1u1, l2u1, r2u1; ROWX(i12 - 1, mu1, l1u1, r1u1, l2u1, r2u1)
        unsigned md1, l1d1, r1d1, l2d1, r2d1; ROWX(i12 + 1, md1, l1d1, r1d1, l2d1, r2d1)
        unsigned mu2, l1u2, r1u2, l2u2, r2u2; ROWX(i12 - 2, mu2, l1u2, r1u2, l2u2, r2u2)
        unsigned md2, l1d2, r1d2, l2d2, r2d2; ROWX(i12 + 2, md2, l1d2, r1d2, l2d2, r2d2)
        #undef ROWX

        unsigned D1 = (l10 & lm1) | (r10 & rm1) | (mu1 & vu1) | (md1 & vd1);
        unsigned D2 = (((l1u1 & lm1) | (r1u1 & rm1)) & vu1)
                    | (((l1d1 & lm1) | (r1d1 & rm1)) & vd1);
        unsigned D4 = (l20 & lm2) | (r20 & rm2) | (mu2 & vu2) | (md2 & vd2);
        unsigned D5 = (((l2u1 & lm2) | (r2u1 & rm2)) & vu1)
                    | (((l2d1 & lm2) | (r2d1 & rm2)) & vd1)
                    | (((l1u2 & lm1) | (r1u2 & rm1)) & vu2)
                    | (((l1d2 & lm1) | (r1d2 & rm1)) & vd2);
        unsigned D8 = (((l2u2 & lm2) | (r2u2 & rm2)) & vu2)
                    | (((l2d2 & lm2) | (r2d2 & rm2)) & vd2);

        unsigned A1m = D1 & T1;
        unsigned R2m = T1 & ~D1;   unsigned A2m = D2 & R2m;
        unsigned R4m = R2m & ~D2;  unsigned A4m = D4 & R4m;
        unsigned R5m = R4m & ~D4;  unsigned A5m = D5 & R5m;
        unsigned R8m = R5m & ~D5;  unsigned A8m = D8 & R8m;
        unsigned U   = R8m & ~D8;

        const float S2 = 1.41421354f;
        const float S5 = 2.23606801f;
        const float S8 = 2.82842708f;

        contrib  = (float)__popc(A1m & ~P);
        contrib += (float)__popc(A2m & ~P) * S2 - (float)__popc(A2m & P) * (S2 - 1.0f);
        contrib += (float)__popc(A4m & ~P) * 2.0f - (float)__popc(A4m & P) * 1.0f;
        contrib += (float)__popc(A5m & ~P) * S5 - (float)__popc(A5m & P) * (S5 - 1.0f);
        contrib += (float)__popc(A8m & ~P) * S8 - (float)__popc(A8m & P) * (S8 - 1.0f);

        while (U) {   // ~never: defer to worklist for the final block
            int jb = __ffs(U) - 1; U &= U - 1;
            int j = wc * 32 + jb;
            int mybit = (P >> jb) & 1;
            int slot = atomicAdd(&g_wl_n, 1);
            if (slot < WLCAP)
                g_wl[slot] = (s << 17) | (i << 9) | (j << 1) | mybit;
        }

        #pragma unroll
        for (int off = 16; off > 0; off >>= 1)
            contrib += __shfl_xor_sync(0xffffffffu, contrib, off);
        if (tid == 0)  s_c[0] = contrib;
        if (tid == 32) s_c[1] = contrib;
    }
    __syncthreads();

    if (tid == 0) {
        atomicAdd(&g_res[s], (double)(s_c[0] + s_c[1]));
        __threadfence();
        unsigned tk = atomicAdd(&g_ticket, 1u);
        s_last = (tk == NB - 1);
    }
    __syncthreads();

    // ---------------- Final block: worklist + finalize ----------------------
    if (s_last) {
        if (tid == 0) __threadfence();
        __syncthreads();
        int n = g_wl_n; if (n > WLCAP) n = WLCAP;
        for (int k = tid; k < n; k += TPB) {
            int e = g_wl[k];
            int es = e >> 17, ei = (e >> 9) & 255, ej = (e >> 1) & 255, eb = e & 1;
            double v = fb_contrib(g_posbits + es * WPS, ei, ej, eb,
                                  g_haspos[es], g_hasneg[es]);
            atomicAdd(&g_res[es], v);
        }
        __syncthreads();
        if (tid == 0) {
            double ce = g_ce / (double)NPIX;
            double dice = 1.0 - (2.0 * (double)g_inter_i + 1.0)
                              / ((double)g_hard_i + (double)g_t_i + 1.0);
            double lb = 0.0;
            #pragma unroll
            for (int q = 0; q < BB; ++q)
                if (g_haspos[q]) lb += g_res[q] / (double)HW;
            float r = (float)(ce + dice + lb * lb);
            for (int k = 0; k < out_size; ++k) out[k] = r;

            g_ce = 0.0; g_hard_i = 0; g_t_i = 0; g_inter_i = 0;
            #pragma unroll
            for (int q = 0; q < BB; ++q) { g_res[q] = 0.0; g_haspos[q] = 0; g_hasneg[q] = 0; }
            g_ticket = 0u; g_wl_n = 0;
        }
    }
}

extern "C" void kernel_launch(void* const* d_in, const int* in_sizes, int n_in,
                              void* d_out, int out_size) {
    const float* inputs  = (const float*)d_in[0];   // (16,2,256,256) f32
    const int*   targets = (const int*)  d_in[1];   // (16,256,256)   i32
    k_fused<<<NB, TPB>>>(inputs, targets, (float*)d_out, out_size);
}